// round 6
// baseline (speedup 1.0000x reference)
#include <cuda_runtime.h>
#include <math_constants.h>

#define GRID 128
#define NCELLS (GRID * GRID)            // 16384
#define MAXN2 16384
#define NB1 64                          // blocks for build-side kernels
#define MAX_RED_BLOCKS 128

// ---------------- device scratch (no allocations allowed) ----------------
__device__ int    g_count[NCELLS];
__device__ int    g_start[NCELLS];
__device__ int    g_cursor[NCELLS];
__device__ float2 g_sorted[MAXN2];
__device__ float  g_bxm[NB1], g_bym[NB1], g_bxM[NB1], g_byM[NB1];
__device__ float  g_box[8];             // x0, y0, sx, sy, cwmin
__device__ float  g_blocksums[MAX_RED_BLOCKS];

// ================= K1: zero counts + per-block pos2 min/max =================
__global__ void __launch_bounds__(256) k_zero_minmax(const float* __restrict__ pos2, int N2)
{
    __shared__ float sxm[256], sym[256], sxM[256], syM[256];
    const int tid = threadIdx.x;
    const int gid = blockIdx.x * 256 + tid;
    const int stride = gridDim.x * 256;

    for (int c = gid; c < NCELLS; c += stride) g_count[c] = 0;

    float xm = CUDART_INF_F, ym = CUDART_INF_F;
    float xM = -CUDART_INF_F, yM = -CUDART_INF_F;
    for (int i = gid; i < N2 && i < MAXN2; i += stride) {
        const float2 p = reinterpret_cast<const float2*>(pos2)[i];
        xm = fminf(xm, p.x); xM = fmaxf(xM, p.x);
        ym = fminf(ym, p.y); yM = fmaxf(yM, p.y);
    }
    sxm[tid] = xm; sym[tid] = ym; sxM[tid] = xM; syM[tid] = yM;
    __syncthreads();
    for (int s = 128; s > 0; s >>= 1) {
        if (tid < s) {
            sxm[tid] = fminf(sxm[tid], sxm[tid + s]);
            sym[tid] = fminf(sym[tid], sym[tid + s]);
            sxM[tid] = fmaxf(sxM[tid], sxM[tid + s]);
            syM[tid] = fmaxf(syM[tid], syM[tid + s]);
        }
        __syncthreads();
    }
    if (tid == 0) {
        g_bxm[blockIdx.x] = sxm[0]; g_bym[blockIdx.x] = sym[0];
        g_bxM[blockIdx.x] = sxM[0]; g_byM[blockIdx.x] = syM[0];
    }
}

// ================= K2: finalize bbox -> grid params =================
__global__ void k_box_finalize()
{
    __shared__ float sxm[NB1], sym[NB1], sxM[NB1], syM[NB1];
    const int tid = threadIdx.x;
    sxm[tid] = g_bxm[tid]; sym[tid] = g_bym[tid];
    sxM[tid] = g_bxM[tid]; syM[tid] = g_byM[tid];
    __syncthreads();
    for (int s = NB1 / 2; s > 0; s >>= 1) {
        if (tid < s) {
            sxm[tid] = fminf(sxm[tid], sxm[tid + s]);
            sym[tid] = fminf(sym[tid], sym[tid + s]);
            sxM[tid] = fmaxf(sxM[tid], sxM[tid + s]);
            syM[tid] = fmaxf(syM[tid], syM[tid + s]);
        }
        __syncthreads();
    }
    if (tid == 0) {
        const float x0 = sxm[0], y0 = sym[0];
        float ex = sxM[0] - x0, ey = syM[0] - y0;
        ex = fmaxf(ex, 1e-6f); ey = fmaxf(ey, 1e-6f);
        const float cw = ex / (float)GRID, ch = ey / (float)GRID;
        g_box[0] = x0;
        g_box[1] = y0;
        g_box[2] = (float)GRID / ex;    // sx
        g_box[3] = (float)GRID / ey;    // sy
        g_box[4] = fminf(cw, ch);       // cwmin (pruning bound)
    }
}

__device__ __forceinline__ int cell_of(float v, float v0, float s)
{
    int c = (int)((v - v0) * s);
    c = c < 0 ? 0 : c;
    return c > GRID - 1 ? GRID - 1 : c;
}

// ================= K3: count points per cell =================
__global__ void __launch_bounds__(256) k_count(const float* __restrict__ pos2, int N2)
{
    const float x0 = g_box[0], y0 = g_box[1], sx = g_box[2], sy = g_box[3];
    const int gid = blockIdx.x * 256 + threadIdx.x;
    const int stride = gridDim.x * 256;
    for (int i = gid; i < N2 && i < MAXN2; i += stride) {
        const float2 p = reinterpret_cast<const float2*>(pos2)[i];
        const int cx = cell_of(p.x, x0, sx);
        const int cy = cell_of(p.y, y0, sy);
        atomicAdd(&g_count[cy * GRID + cx], 1);
    }
}

// ================= K4: exclusive scan over 16384 cells (1 block) =================
__global__ void __launch_bounds__(1024) k_scan()
{
    __shared__ int sh[1024];
    const int tid = threadIdx.x;
    const int base = tid * (NCELLS / 1024);    // 16 cells per thread

    int c[NCELLS / 1024];
    int sum = 0;
#pragma unroll
    for (int k = 0; k < NCELLS / 1024; k++) {
        c[k] = g_count[base + k];
        sum += c[k];
    }
    sh[tid] = sum;
    __syncthreads();
    // inclusive Hillis-Steele scan over 1024 thread-sums
    for (int off = 1; off < 1024; off <<= 1) {
        int v = (tid >= off) ? sh[tid - off] : 0;
        __syncthreads();
        sh[tid] += v;
        __syncthreads();
    }
    int run = sh[tid] - sum;                   // exclusive base
#pragma unroll
    for (int k = 0; k < NCELLS / 1024; k++) {
        g_start[base + k] = run;
        g_cursor[base + k] = run;
        run += c[k];
    }
}

// ================= K5: scatter pos2 into cell-sorted order =================
__global__ void __launch_bounds__(256) k_scatter(const float* __restrict__ pos2, int N2)
{
    const float x0 = g_box[0], y0 = g_box[1], sx = g_box[2], sy = g_box[3];
    const int gid = blockIdx.x * 256 + threadIdx.x;
    const int stride = gridDim.x * 256;
    for (int i = gid; i < N2 && i < MAXN2; i += stride) {
        const float2 p = reinterpret_cast<const float2*>(pos2)[i];
        const int cx = cell_of(p.x, x0, sx);
        const int cy = cell_of(p.y, y0, sy);
        const int pos = atomicAdd(&g_cursor[cy * GRID + cx], 1);
        g_sorted[pos] = p;
    }
}

// ================= K6: ring-search query + block partial sums =================
__device__ __forceinline__ void scan_cell(int cxx, int cyy, float qx, float qy, float& best)
{
    const int c = cyy * GRID + cxx;
    const int s = g_start[c];
    const int e = s + g_count[c];
    for (int k = s; k < e; k++) {
        const float2 p = g_sorted[k];
        const float dx = qx - p.x;
        const float dy = qy - p.y;
        const float d2 = fmaf(dx, dx, dy * dy);
        best = fminf(best, d2);
    }
}

__global__ void __launch_bounds__(256) k_query(const float* __restrict__ pos1, int N1)
{
    const float x0 = g_box[0], y0 = g_box[1], sx = g_box[2], sy = g_box[3];
    const float cwmin = g_box[4];

    const int gid = blockIdx.x * 256 + threadIdx.x;
    const int stride = gridDim.x * 256;

    float acc = 0.0f;   // sum of sqrt(best) over this thread's queries
    for (int i = gid; i < N1; i += stride) {
        const float2 q = reinterpret_cast<const float2*>(pos1)[i];
        const int cx = cell_of(q.x, x0, sx);
        const int cy = cell_of(q.y, y0, sy);

        float best = CUDART_INF_F;
        for (int r = 0; r <= 2 * GRID; r++) {
            if (r == 0) {
                scan_cell(cx, cy, q.x, q.y, best);
            } else {
                const int xlo = max(cx - r, 0), xhi = min(cx + r, GRID - 1);
                if (cy - r >= 0)
                    for (int x = xlo; x <= xhi; x++) scan_cell(x, cy - r, q.x, q.y, best);
                if (cy + r <= GRID - 1)
                    for (int x = xlo; x <= xhi; x++) scan_cell(x, cy + r, q.x, q.y, best);
                const int ylo = max(cy - r + 1, 0), yhi = min(cy + r - 1, GRID - 1);
                if (cx - r >= 0)
                    for (int y = ylo; y <= yhi; y++) scan_cell(cx - r, y, q.x, q.y, best);
                if (cx + r <= GRID - 1)
                    for (int y = ylo; y <= yhi; y++) scan_cell(cx + r, y, q.x, q.y, best);
            }
            // after completing rings 0..r, unexamined cells are at ring >= r+1,
            // whose minimum distance is >= r * cwmin
            const float bound = (float)r * cwmin;
            if (best <= bound * bound) break;
            // full grid covered -> nothing left
            if (cx - r <= 0 && cy - r <= 0 && cx + r >= GRID - 1 && cy + r >= GRID - 1) break;
        }
        acc += sqrtf(best);
    }

    __shared__ float red[256];
    red[threadIdx.x] = acc;
    __syncthreads();
#pragma unroll
    for (int s = 128; s > 0; s >>= 1) {
        if (threadIdx.x < s) red[threadIdx.x] += red[threadIdx.x + s];
        __syncthreads();
    }
    if (threadIdx.x == 0) g_blocksums[blockIdx.x] = red[0];
}

// ================= K7: final deterministic sum + mean =================
__global__ void k_final(float* __restrict__ out, int nblocks, float inv_n)
{
    __shared__ float red[MAX_RED_BLOCKS];
    const int tid = threadIdx.x;
    red[tid] = (tid < nblocks) ? g_blocksums[tid] : 0.0f;
    __syncthreads();
#pragma unroll
    for (int s = MAX_RED_BLOCKS / 2; s > 0; s >>= 1) {
        if (tid < s) red[tid] += red[tid + s];
        __syncthreads();
    }
    if (tid == 0) out[0] = red[0] * inv_n;
}

// ================= launch =================
extern "C" void kernel_launch(void* const* d_in, const int* in_sizes, int n_in,
                              void* d_out, int out_size)
{
    const float* pos1 = (const float*)d_in[0];
    const float* pos2 = (const float*)d_in[1];
    float* out = (float*)d_out;

    const int N1 = in_sizes[0] / 2;
    const int N2 = in_sizes[1] / 2;

    k_zero_minmax<<<NB1, 256>>>(pos2, N2);
    k_box_finalize<<<1, NB1>>>();
    k_count<<<NB1, 256>>>(pos2, N2);
    k_scan<<<1, 1024>>>();
    k_scatter<<<NB1, 256>>>(pos2, N2);

    int qblocks = (N1 + 255) / 256;
    if (qblocks > MAX_RED_BLOCKS) qblocks = MAX_RED_BLOCKS;
    k_query<<<qblocks, 256>>>(pos1, N1);

    k_final<<<1, MAX_RED_BLOCKS>>>(out, qblocks, 1.0f / (float)N1);
}